// round 4
// baseline (speedup 1.0000x reference)
#include <cuda_runtime.h>
#include <math.h>
#include <stdint.h>

#define BATCH 2
#define SEQ   2048
#define EMB   1024
#define NH    16
#define HD    64
#define M1    (BATCH*SEQ)   /* 4096 */
#define N1    (3*EMB)       /* 3072 */
#define KDIM  1024
#define KT    16            /* gemm k-tile */
#define PA    136           /* smem pitch (4B units); 136 mod 32 == 8 -> conflict-free frags */

// ---------------- device scratch (allocation-free rule) ----------------
__device__ float    g_Q  [(size_t)BATCH*NH*SEQ*HD];   // [b,h,s,d] fp32
__device__ uint32_t g_KTh[(size_t)BATCH*NH*HD*SEQ];   // [b,h,d,s] tf32 hi
__device__ uint32_t g_KTl[(size_t)BATCH*NH*HD*SEQ];   // tf32 lo
__device__ float    g_V  [(size_t)BATCH*NH*SEQ*HD];   // [b,h,s,d] fp32
__device__ float    g_AO [(size_t)BATCH*SEQ*EMB];     // attended [b,s,e]

__device__ uint32_t g_xth [(size_t)KDIM*M1];          // x^T split hi  [k][m]
__device__ uint32_t g_xtl [(size_t)KDIM*M1];
__device__ uint32_t g_aoth[(size_t)KDIM*M1];          // AO^T split hi [k][m]
__device__ uint32_t g_aotl[(size_t)KDIM*M1];
__device__ uint32_t g_wqh [(size_t)KDIM*N1];          // Wqkv split [k][n]
__device__ uint32_t g_wql [(size_t)KDIM*N1];
__device__ uint32_t g_woh [(size_t)KDIM*EMB];         // Wout split [k][n]
__device__ uint32_t g_wol [(size_t)KDIM*EMB];

__device__ __forceinline__ uint32_t f2tf32(float v) {
    uint32_t r;
    asm("cvt.rna.tf32.f32 %0, %1;" : "=r"(r) : "f"(v));
    return r;
}

#define MMA(C, A0, A1, A2, A3, B0, B1)                                        \
    asm volatile(                                                             \
        "mma.sync.aligned.m16n8k8.row.col.f32.tf32.tf32.f32 "                 \
        "{%0,%1,%2,%3}, {%4,%5,%6,%7}, {%8,%9}, {%0,%1,%2,%3};"               \
        : "+f"((C)[0]), "+f"((C)[1]), "+f"((C)[2]), "+f"((C)[3])              \
        : "r"(A0), "r"(A1), "r"(A2), "r"(A3), "r"(B0), "r"(B1))

#define CPA16(dst_u32, src_ptr)                                               \
    asm volatile("cp.async.cg.shared.global [%0], [%1], 16;"                  \
                 :: "r"(dst_u32), "l"(src_ptr))

// ---------------------------------------------------------------------------
// Prep: elementwise split (weights, [k][n] layout kept)
// ---------------------------------------------------------------------------
__global__ __launch_bounds__(256)
void split_w(const float4* __restrict__ W, uint4* __restrict__ Wh,
             uint4* __restrict__ Wl, int n4)
{
    const int i = blockIdx.x * 256 + threadIdx.x;
    if (i >= n4) return;
    const float4 v = W[i];
    const uint32_t h0 = f2tf32(v.x), h1 = f2tf32(v.y), h2 = f2tf32(v.z), h3 = f2tf32(v.w);
    Wh[i] = make_uint4(h0, h1, h2, h3);
    Wl[i] = make_uint4(f2tf32(v.x - __uint_as_float(h0)),
                       f2tf32(v.y - __uint_as_float(h1)),
                       f2tf32(v.z - __uint_as_float(h2)),
                       f2tf32(v.w - __uint_as_float(h3)));
}

// ---------------------------------------------------------------------------
// Prep: split + transpose  X[M][K] -> XT_h/XT_l [K][M]
// ---------------------------------------------------------------------------
__global__ __launch_bounds__(256)
void split_t(const float* __restrict__ X, uint32_t* __restrict__ XTh,
             uint32_t* __restrict__ XTl, int M, int K)
{
    __shared__ float t[32][33];
    const int k0 = blockIdx.x * 32;
    const int m0 = blockIdx.y * 32;
    const int tx = threadIdx.x & 31, ty = threadIdx.x >> 5;
#pragma unroll
    for (int i = 0; i < 4; i++)
        t[ty + i * 8][tx] = X[(size_t)(m0 + ty + i * 8) * K + k0 + tx];
    __syncthreads();
#pragma unroll
    for (int i = 0; i < 4; i++) {
        const float v = t[tx][ty + i * 8];
        const uint32_t hi = f2tf32(v);
        const size_t dst = (size_t)(k0 + ty + i * 8) * M + m0 + tx;
        XTh[dst] = hi;
        XTl[dst] = f2tf32(v - __uint_as_float(hi));
    }
}

// ---------------------------------------------------------------------------
// 3xTF32 GEMM on pre-split operands, cp.async double-buffered.
// A: [K][M] hi/lo, B: [K][N] hi/lo.
// MODE 0: +bias, scatter to g_Q / g_KTh|l / g_V.   MODE 1: +bias, dense out.
// ---------------------------------------------------------------------------
template<int MODE>
__global__ __launch_bounds__(256, 2)
void gemm_ts(const uint32_t* __restrict__ ATh, const uint32_t* __restrict__ ATl,
             const uint32_t* __restrict__ Bh,  const uint32_t* __restrict__ Bl,
             const float* __restrict__ bias, float* __restrict__ Cout,
             int M, int N, int K)
{
    extern __shared__ uint32_t smu[];
    uint32_t* sAh = smu;                   // [2][KT*PA]
    uint32_t* sAl = sAh + 2 * KT * PA;
    uint32_t* sBh = sAl + 2 * KT * PA;
    uint32_t* sBl = sBh + 2 * KT * PA;

    const int tid  = threadIdx.x;
    const int lane = tid & 31;
    const int wid  = tid >> 5;
    const int mw   = (wid >> 2) * 64;
    const int nw   = (wid & 3) * 32;
    const int g    = lane >> 2;
    const int tig  = lane & 3;
    const int bm   = blockIdx.y * 128;
    const int bn   = blockIdx.x * 128;

    const uint32_t bAh = (uint32_t)__cvta_generic_to_shared(sAh);
    const uint32_t bAl = (uint32_t)__cvta_generic_to_shared(sAl);
    const uint32_t bBh = (uint32_t)__cvta_generic_to_shared(sBh);
    const uint32_t bBl = (uint32_t)__cvta_generic_to_shared(sBl);

    const int c0k  = (tid + 0)   >> 5, c0m = ((tid + 0)   & 31) * 4;
    const int c1k  = (tid + 256) >> 5, c1m = ((tid + 256) & 31) * 4;

    auto issue = [&](int kt) {
        const int buf = kt & 1;
        const int ko  = kt * KT;
        {
            const size_t ga = (size_t)(ko + c0k) * M + bm + c0m;
            const size_t gb = (size_t)(ko + c0k) * N + bn + c0m;
            const uint32_t so = (uint32_t)(buf * KT * PA + c0k * PA + c0m) * 4u;
            CPA16(bAh + so, ATh + ga);
            CPA16(bAl + so, ATl + ga);
            CPA16(bBh + so, Bh + gb);
            CPA16(bBl + so, Bl + gb);
        }
        {
            const size_t ga = (size_t)(ko + c1k) * M + bm + c1m;
            const size_t gb = (size_t)(ko + c1k) * N + bn + c1m;
            const uint32_t so = (uint32_t)(buf * KT * PA + c1k * PA + c1m) * 4u;
            CPA16(bAh + so, ATh + ga);
            CPA16(bAl + so, ATl + ga);
            CPA16(bBh + so, Bh + gb);
            CPA16(bBl + so, Bl + gb);
        }
        asm volatile("cp.async.commit_group;");
    };

    float c[4][4][4];
#pragma unroll
    for (int i = 0; i < 4; i++)
#pragma unroll
        for (int j = 0; j < 4; j++)
#pragma unroll
            for (int l = 0; l < 4; l++) c[i][j][l] = 0.f;

    const int NKT = K / KT;
    issue(0);

    for (int kt = 0; kt < NKT; kt++) {
        if (kt + 1 < NKT) {
            issue(kt + 1);
            asm volatile("cp.async.wait_group 1;");
        } else {
            asm volatile("cp.async.wait_group 0;");
        }
        __syncthreads();

        const int cur = kt & 1;
        const uint32_t* ah = sAh + cur * KT * PA;
        const uint32_t* al = sAl + cur * KT * PA;
        const uint32_t* bh = sBh + cur * KT * PA;
        const uint32_t* bl = sBl + cur * KT * PA;

#pragma unroll
        for (int ks = 0; ks < KT; ks += 8) {
            const int kA0 = ks + tig, kA1 = ks + tig + 4;
            uint32_t bhf[4][2], blf[4][2];
#pragma unroll
            for (int ni = 0; ni < 4; ni++) {
                const int n = nw + ni * 8 + g;
                bhf[ni][0] = bh[kA0 * PA + n];
                bhf[ni][1] = bh[kA1 * PA + n];
                blf[ni][0] = bl[kA0 * PA + n];
                blf[ni][1] = bl[kA1 * PA + n];
            }
#pragma unroll
            for (int mi = 0; mi < 4; mi++) {
                const int r0 = mw + mi * 16 + g, r1 = r0 + 8;
                const uint32_t ah0 = ah[kA0 * PA + r0];
                const uint32_t ah1 = ah[kA0 * PA + r1];
                const uint32_t ah2 = ah[kA1 * PA + r0];
                const uint32_t ah3 = ah[kA1 * PA + r1];
                const uint32_t al0 = al[kA0 * PA + r0];
                const uint32_t al1 = al[kA0 * PA + r1];
                const uint32_t al2 = al[kA1 * PA + r0];
                const uint32_t al3 = al[kA1 * PA + r1];
#pragma unroll
                for (int ni = 0; ni < 4; ni++) {
                    MMA(c[mi][ni], ah0, ah1, ah2, ah3, bhf[ni][0], bhf[ni][1]);
                    MMA(c[mi][ni], ah0, ah1, ah2, ah3, blf[ni][0], blf[ni][1]);
                    MMA(c[mi][ni], al0, al1, al2, al3, bhf[ni][0], bhf[ni][1]);
                }
            }
        }
        __syncthreads();
    }

    // ---- epilogue ----
#pragma unroll
    for (int mi = 0; mi < 4; mi++) {
#pragma unroll
        for (int ni = 0; ni < 4; ni++) {
            const int r0 = bm + mw + mi * 16 + g;
            const int r1 = r0 + 8;
            const int n0 = bn + nw + ni * 8 + tig * 2;
            const float bv0 = bias[n0], bv1 = bias[n0 + 1];
            const float v00 = c[mi][ni][0] + bv0;
            const float v01 = c[mi][ni][1] + bv1;
            const float v10 = c[mi][ni][2] + bv0;
            const float v11 = c[mi][ni][3] + bv1;
            if (MODE == 1) {
                *(float2*)&Cout[(size_t)r0 * N + n0] = make_float2(v00, v01);
                *(float2*)&Cout[(size_t)r1 * N + n0] = make_float2(v10, v11);
            } else {
#pragma unroll
                for (int e2 = 0; e2 < 4; e2++) {
                    const int m = (e2 < 2) ? r0 : r1;
                    const int n = n0 + (e2 & 1);
                    const float v = (e2 == 0) ? v00 : (e2 == 1) ? v01 : (e2 == 2) ? v10 : v11;
                    const int b = m >> 11, s = m & (SEQ - 1);
                    const int type = n >> 10, e = n & (EMB - 1);
                    const int h = e >> 6, d = e & 63;
                    const size_t bh = (size_t)(b * NH + h);
                    if (type == 0)      g_Q[(bh * SEQ + s) * HD + d] = v;
                    else if (type == 1) {
                        const size_t ix = (bh * HD + d) * SEQ + s;
                        const uint32_t hi = f2tf32(v);
                        g_KTh[ix] = hi;
                        g_KTl[ix] = f2tf32(v - __uint_as_float(hi));
                    }
                    else                g_V[(bh * SEQ + s) * HD + d] = v;
                }
            }
        }
    }
}

// ---------------------------------------------------------------------------
// Tensor-core causal attention: S computed ONCE.
// Pass 1: S = QK^T (3xTF32), online (m,l), raw masked S -> attw (scratch).
// Pass 2: re-read S, P = exp(s-m)/l -> attw + smem, O += P@V (1x tf32).
// CTA = 128 q-rows of one (b,h), 8 warps.
// ---------------------------------------------------------------------------
#define PQ 68
#define O_QH 0
#define O_QL 8704
#define O_KH 17408
#define O_KL 21760
#define O_VT 26112
#define O_PM 30464
#define O_Mr 39168
#define O_Li 39296
#define ATTN_SMEM_F 39424

__global__ __launch_bounds__(256)
void attn2(float* __restrict__ attw)
{
    extern __shared__ float smf[];
    uint32_t* smu = (uint32_t*)smf;

    const int tid  = threadIdx.x;
    const int lane = tid & 31;
    const int wid  = tid >> 5;
    const int g    = lane >> 2;
    const int tig  = lane & 3;
    const int band = wid * 16;
    const int q0   = (gridDim.x - 1 - blockIdx.x) * 128;  // heavy tiles first
    const int bh   = blockIdx.y;

    const float* Qg = g_Q + ((size_t)bh * SEQ + q0) * HD;
    const float* Vg = g_V + (size_t)bh * SEQ * HD;
    const size_t kbase = (size_t)bh * HD * SEQ;

    // ---- Q tile (128x64), scale 1/8, split hi/lo ----
#pragma unroll
    for (int i = 0; i < 8; i++) {
        const int idx = tid + i * 256;
        const int r = idx >> 4, c4 = idx & 15;
        float4 v = *(const float4*)&Qg[(size_t)r * HD + c4 * 4];
        v.x *= 0.125f; v.y *= 0.125f; v.z *= 0.125f; v.w *= 0.125f;
        uint32_t h0 = f2tf32(v.x), h1 = f2tf32(v.y), h2 = f2tf32(v.z), h3 = f2tf32(v.w);
        *(uint4*)&smu[O_QH + r * PQ + c4 * 4] = make_uint4(h0, h1, h2, h3);
        *(uint4*)&smu[O_QL + r * PQ + c4 * 4] =
            make_uint4(f2tf32(v.x - __uint_as_float(h0)),
                       f2tf32(v.y - __uint_as_float(h1)),
                       f2tf32(v.z - __uint_as_float(h2)),
                       f2tf32(v.w - __uint_as_float(h3)));
    }

    const int nch  = (q0 >> 6) + 2;
    const int row0 = q0 + band + g;
    const int row1 = row0 + 8;
    float* Prow = attw + ((size_t)bh * SEQ + q0) * SEQ;

    float m0 = -1e30f, m1 = -1e30f, l0 = 0.f, l1 = 0.f;

    // =============================== PASS 1 ===============================
    for (int kc = 0; kc < nch; kc++) {
        const int s0 = kc * 64;
        __syncthreads();
#pragma unroll
        for (int i = 0; i < 4; i++) {
            const int idx = tid + i * 256;
            const int d = idx >> 4, c4 = idx & 15;
            const size_t gk = kbase + (size_t)d * SEQ + s0 + c4 * 4;
            *(uint4*)&smu[O_KH + d * PQ + c4 * 4] = *(const uint4*)&g_KTh[gk];
            *(uint4*)&smu[O_KL + d * PQ + c4 * 4] = *(const uint4*)&g_KTl[gk];
        }
        __syncthreads();

        float sc[8][4];
#pragma unroll
        for (int nf = 0; nf < 8; nf++)
#pragma unroll
            for (int j = 0; j < 4; j++) sc[nf][j] = 0.f;

#pragma unroll
        for (int k8 = 0; k8 < 8; k8++) {
            const int ka = k8 * 8 + tig;
            const uint32_t ah0 = smu[O_QH + (band + g) * PQ + ka];
            const uint32_t ah1 = smu[O_QH + (band + g + 8) * PQ + ka];
            const uint32_t ah2 = smu[O_QH + (band + g) * PQ + ka + 4];
            const uint32_t ah3 = smu[O_QH + (band + g + 8) * PQ + ka + 4];
            const uint32_t al0 = smu[O_QL + (band + g) * PQ + ka];
            const uint32_t al1 = smu[O_QL + (band + g + 8) * PQ + ka];
            const uint32_t al2 = smu[O_QL + (band + g) * PQ + ka + 4];
            const uint32_t al3 = smu[O_QL + (band + g + 8) * PQ + ka + 4];
#pragma unroll
            for (int nf = 0; nf < 8; nf++) {
                const uint32_t kb0 = smu[O_KH + ka * PQ + nf * 8 + g];
                const uint32_t kb1 = smu[O_KH + (ka + 4) * PQ + nf * 8 + g];
                const uint32_t kl0 = smu[O_KL + ka * PQ + nf * 8 + g];
                const uint32_t kl1 = smu[O_KL + (ka + 4) * PQ + nf * 8 + g];
                MMA(sc[nf], ah0, ah1, ah2, ah3, kb0, kb1);
                MMA(sc[nf], ah0, ah1, ah2, ah3, kl0, kl1);
                MMA(sc[nf], al0, al1, al2, al3, kb0, kb1);
            }
        }

        // mask, online stats, store raw S
        float cm0 = -1e30f, cm1 = -1e30f;
#pragma unroll
        for (int nf = 0; nf < 8; nf++) {
            const int c01 = s0 + nf * 8 + 2 * tig;
            if (c01     > row0) sc[nf][0] = -1e30f;
            if (c01 + 1 > row0) sc[nf][1] = -1e30f;
            if (c01     > row1) sc[nf][2] = -1e30f;
            if (c01 + 1 > row1) sc[nf][3] = -1e30f;
            cm0 = fmaxf(cm0, fmaxf(sc[nf][0], sc[nf][1]));
            cm1 = fmaxf(cm1, fmaxf(sc[nf][2], sc[nf][3]));
        }
#pragma unroll
        for (int nf = 0; nf < 8; nf++) {
            const int c01 = s0 + nf * 8 + 2 * tig;
            *(float2*)&Prow[(size_t)(band + g) * SEQ + c01]     = make_float2(sc[nf][0], sc[nf][1]);
            *(float2*)&Prow[(size_t)(band + g + 8) * SEQ + c01] = make_float2(sc[nf][2], sc[nf][3]);
        }
        cm0 = fmaxf(cm0, __shfl_xor_sync(0xffffffffu, cm0, 1));
        cm0 = fmaxf(cm0, __shfl_xor_sync(0xffffffffu, cm0, 2));
        cm1 = fmaxf(cm1, __shfl_xor_sync(0xffffffffu, cm1, 1));
        cm1 = fmaxf(cm1, __shfl_xor_sync(0xffffffffu, cm1, 2));
        const float mn0 = fmaxf(m0, cm0), mn1 = fmaxf(m1, cm1);
        float s0a = 0.f, s1a = 0.f;
#pragma unroll
        for (int nf = 0; nf < 8; nf++) {
            s0a += __expf(sc[nf][0] - mn0) + __expf(sc[nf][1] - mn0);
            s1a += __expf(sc[nf][2] - mn1) + __expf(sc[nf][3] - mn1);
        }
        s0a += __shfl_xor_sync(0xffffffffu, s0a, 1);
        s0a += __shfl_xor_sync(0xffffffffu, s0a, 2);
        s1a += __shfl_xor_sync(0xffffffffu, s1a, 1);
        s1a += __shfl_xor_sync(0xffffffffu, s1a, 2);
        l0 = l0 * __expf(m0 - mn0) + s0a;
        l1 = l1 * __expf(m1 - mn1) + s1a;
        m0 = mn0; m1 = mn1;
    }

    if (tig == 0) {
        smf[O_Mr + band + g]     = m0;
        smf[O_Mr + band + g + 8] = m1;
        smf[O_Li + band + g]     = 1.f / l0;
        smf[O_Li + band + g + 8] = 1.f / l1;
    }

    // =============================== PASS 2 ===============================
    float co[8][4];
#pragma unroll
    for (int df = 0; df < 8; df++)
#pragma unroll
        for (int j = 0; j < 4; j++) co[df][j] = 0.f;

    for (int kc = 0; kc < nch; kc++) {
        const int s0 = kc * 64;
        __syncthreads();
        // V tile (tf32)
#pragma unroll
        for (int i = 0; i < 4; i++) {
            const int idx = tid + i * 256;
            const int key = idx >> 4, c4 = idx & 15;
            const float4 vv = *(const float4*)&Vg[(size_t)(s0 + key) * HD + c4 * 4];
            *(uint4*)&smu[O_VT + key * PQ + c4 * 4] =
                make_uint4(f2tf32(vv.x), f2tf32(vv.y), f2tf32(vv.z), f2tf32(vv.w));
        }
        // S -> P (read S from gmem, exp-normalize, write to smem + gmem)
#pragma unroll
        for (int i = 0; i < 8; i++) {
            const int idx = tid + i * 256;
            const int r = idx >> 4, c4 = idx & 15;
            float4 s4 = *(const float4*)&Prow[(size_t)r * SEQ + s0 + c4 * 4];
            const float mr = smf[O_Mr + r];
            const float il = smf[O_Li + r];
            s4.x = __expf(s4.x - mr) * il;
            s4.y = __expf(s4.y - mr) * il;
            s4.z = __expf(s4.z - mr) * il;
            s4.w = __expf(s4.w - mr) * il;
            *(float4*)&smf[O_PM + r * PQ + c4 * 4] = s4;
            *(float4*)&Prow[(size_t)r * SEQ + s0 + c4 * 4] = s4;
        }
        __syncthreads();

        // O += P @ V
#pragma unroll
        for (int k8 = 0; k8 < 8; k8++) {
            const int ka = k8 * 8 + tig;
            const uint32_t a0 = f2tf32(smf[O_PM + (band + g) * PQ + ka]);
            const uint32_t a1 = f2tf32(smf[O_PM + (band + g + 8) * PQ + ka]);
            const uint32_t a2 = f2tf32(smf[O_PM + (band + g) * PQ + ka + 4]);
            const uint32_t a3 = f2tf32(smf[O_PM + (band + g + 8) * PQ + ka + 4]);
#pragma unroll
            for (int df = 0; df < 8; df++) {
                const uint32_t b0 = smu[O_VT + ka * PQ + df * 8 + g];
                const uint32_t b1 = smu[O_VT + (ka + 4) * PQ + df * 8 + g];
                MMA(co[df], a0, a1, a2, a3, b0, b1);
            }
        }
    }

    // ---- zero tail of attention_weights ----
    {
        const int ztail = nch * 64;                // == q0 + 128
        const int ncol4 = (SEQ - ztail) >> 2;
        const float4 z = make_float4(0.f, 0.f, 0.f, 0.f);
        for (int idx = tid; idx < 128 * ncol4; idx += 256) {
            const int r = idx / ncol4, c = idx - r * ncol4;
            *(float4*)&Prow[(size_t)r * SEQ + ztail + c * 4] = z;
        }
    }

    // ---- write O ----
    {
        const int b = bh >> 4, h = bh & 15;
#pragma unroll
        for (int df = 0; df < 8; df++) {
            const int d = h * 64 + df * 8 + 2 * tig;
            *(float2*)&g_AO[(size_t)(b * SEQ + row0) * EMB + d] = make_float2(co[df][0], co[df][1]);
            *(float2*)&g_AO[(size_t)(b * SEQ + row1) * EMB + d] = make_float2(co[df][2], co[df][3]);
        }
    }
}

// ---------------------------------------------------------------------------
extern "C" void kernel_launch(void* const* d_in, const int* in_sizes, int n_in,
                              void* d_out, int out_size)
{
    const float* x    = (const float*)d_in[0];
    const float* Wqkv = (const float*)d_in[1];
    const float* bqkv = (const float*)d_in[2];
    const float* Wout = (const float*)d_in[3];
    const float* bout = (const float*)d_in[4];

    float* out  = (float*)d_out;
    float* attw = out + (size_t)BATCH * SEQ * EMB;

    uint32_t *p_xth, *p_xtl, *p_aoth, *p_aotl, *p_wqh, *p_wql, *p_woh, *p_wol;
    cudaGetSymbolAddress((void**)&p_xth,  g_xth);
    cudaGetSymbolAddress((void**)&p_xtl,  g_xtl);
    cudaGetSymbolAddress((void**)&p_aoth, g_aoth);
    cudaGetSymbolAddress((void**)&p_aotl, g_aotl);
    cudaGetSymbolAddress((void**)&p_wqh,  g_wqh);
    cudaGetSymbolAddress((void**)&p_wql,  g_wql);
    cudaGetSymbolAddress((void**)&p_woh,  g_woh);
    cudaGetSymbolAddress((void**)&p_wol,  g_wol);
    float* p_ao;
    cudaGetSymbolAddress((void**)&p_ao, g_AO);

    const int gsmem = 8 * KT * PA * (int)sizeof(uint32_t);   // 69632
    cudaFuncSetAttribute(gemm_ts<0>, cudaFuncAttributeMaxDynamicSharedMemorySize, gsmem);
    cudaFuncSetAttribute(gemm_ts<1>, cudaFuncAttributeMaxDynamicSharedMemorySize, gsmem);
    const int asmem = ATTN_SMEM_F * (int)sizeof(float);      // 157696
    cudaFuncSetAttribute(attn2, cudaFuncAttributeMaxDynamicSharedMemorySize, asmem);

    // prep: split weights + split-transpose x
    split_w<<<(KDIM * N1 / 4 + 255) / 256, 256>>>((const float4*)Wqkv, (uint4*)p_wqh, (uint4*)p_wql, KDIM * N1 / 4);
    split_w<<<(KDIM * EMB / 4 + 255) / 256, 256>>>((const float4*)Wout, (uint4*)p_woh, (uint4*)p_wol, KDIM * EMB / 4);
    split_t<<<dim3(KDIM / 32, M1 / 32), 256>>>(x, p_xth, p_xtl, M1, KDIM);

    // 1) QKV projection
    gemm_ts<0><<<dim3(N1 / 128, M1 / 128), 256, gsmem>>>(p_xth, p_xtl, p_wqh, p_wql, bqkv, nullptr, M1, N1, KDIM);

    // 2) fused causal attention (writes attention_weights)
    attn2<<<dim3(SEQ / 128, BATCH * NH), 256, asmem>>>(attw);

    // prep: split-transpose attended output
    split_t<<<dim3(KDIM / 32, M1 / 32), 256>>>(p_ao, p_aoth, p_aotl, M1, KDIM);

    // 3) output projection
    gemm_ts<1><<<dim3(EMB / 128, M1 / 128), 256, gsmem>>>(p_aoth, p_aotl, p_woh, p_wol, bout, out, M1, EMB, KDIM);
}

// round 5
// speedup vs baseline: 1.9028x; 1.9028x over previous
#include <cuda_runtime.h>
#include <cuda_bf16.h>
#include <math.h>
#include <stdint.h>

#define BATCH 2
#define SEQ   2048
#define EMB   1024
#define NH    16
#define HD    64
#define M1    (BATCH*SEQ)   /* 4096 */
#define N1    (3*EMB)       /* 3072 */
#define KDIM  1024
#define PA    136           /* gemm smem pitch (words); 136%32==8 -> conflict-free frags */

// ---------------- device scratch (allocation-free rule) ----------------
__device__ float    g_Q  [(size_t)BATCH*NH*SEQ*HD];     // [b,h,s,d] fp32
__device__ uint32_t g_KTh[(size_t)BATCH*NH*(HD/2)*SEQ]; // [b,h,d/2,s] packed bf16 hi
__device__ uint32_t g_KTl[(size_t)BATCH*NH*(HD/2)*SEQ]; // packed bf16 lo
__device__ float    g_V  [(size_t)BATCH*NH*SEQ*HD];     // [b,h,s,d] fp32
__device__ float    g_AO [(size_t)BATCH*SEQ*EMB];       // attended [b,s,e]

__device__ uint32_t g_xth [(size_t)(KDIM/2)*M1];        // x^T packed hi  [k/2][m]
__device__ uint32_t g_xtl [(size_t)(KDIM/2)*M1];
__device__ uint32_t g_aoth[(size_t)(KDIM/2)*M1];        // AO^T packed [k/2][m]
__device__ uint32_t g_aotl[(size_t)(KDIM/2)*M1];
__device__ uint32_t g_wqh [(size_t)(KDIM/2)*N1];        // Wqkv packed [k/2][n]
__device__ uint32_t g_wql [(size_t)(KDIM/2)*N1];
__device__ uint32_t g_woh [(size_t)(KDIM/2)*EMB];       // Wout packed [k/2][n]
__device__ uint32_t g_wol [(size_t)(KDIM/2)*EMB];

__device__ __forceinline__ uint32_t f2tf32(float v) {
    uint32_t r;
    asm("cvt.rna.tf32.f32 %0, %1;" : "=r"(r) : "f"(v));
    return r;
}

// split (v0,v1) -> packed bf16 hi/lo words; v0 (even k) in low half
__device__ __forceinline__ void split_pack(float v0, float v1,
                                           uint32_t& hi, uint32_t& lo)
{
    const __nv_bfloat16 h0 = __float2bfloat16(v0);
    const __nv_bfloat16 h1 = __float2bfloat16(v1);
    const __nv_bfloat16 l0 = __float2bfloat16(v0 - __bfloat162float(h0));
    const __nv_bfloat16 l1 = __float2bfloat16(v1 - __bfloat162float(h1));
    hi = ((uint32_t)__bfloat16_as_ushort(h1) << 16) | __bfloat16_as_ushort(h0);
    lo = ((uint32_t)__bfloat16_as_ushort(l1) << 16) | __bfloat16_as_ushort(l0);
}

#define MMA16(C, A0, A1, A2, A3, B0, B1)                                      \
    asm volatile(                                                             \
        "mma.sync.aligned.m16n8k16.row.col.f32.bf16.bf16.f32 "                \
        "{%0,%1,%2,%3}, {%4,%5,%6,%7}, {%8,%9}, {%0,%1,%2,%3};"               \
        : "+f"((C)[0]), "+f"((C)[1]), "+f"((C)[2]), "+f"((C)[3])              \
        : "r"(A0), "r"(A1), "r"(A2), "r"(A3), "r"(B0), "r"(B1))

#define MMA8(C, A0, A1, A2, A3, B0, B1)                                       \
    asm volatile(                                                             \
        "mma.sync.aligned.m16n8k8.row.col.f32.tf32.tf32.f32 "                 \
        "{%0,%1,%2,%3}, {%4,%5,%6,%7}, {%8,%9}, {%0,%1,%2,%3};"               \
        : "+f"((C)[0]), "+f"((C)[1]), "+f"((C)[2]), "+f"((C)[3])              \
        : "r"(A0), "r"(A1), "r"(A2), "r"(A3), "r"(B0), "r"(B1))

#define CPA16(dst_u32, src_ptr)                                               \
    asm volatile("cp.async.cg.shared.global [%0], [%1], 16;"                  \
                 :: "r"(dst_u32), "l"(src_ptr))

// ---------------------------------------------------------------------------
// Prep: W[k][n] fp32 -> packed bf16 hi/lo [k/2][n]
// ---------------------------------------------------------------------------
__global__ __launch_bounds__(256)
void split_w(const float* __restrict__ W, uint32_t* __restrict__ Wh,
             uint32_t* __restrict__ Wl, int N, int total4)
{
    const int i = blockIdx.x * 256 + threadIdx.x;
    if (i >= total4) return;
    const int nw4 = N >> 2;
    const int kp = i / nw4;
    const int n0 = (i - kp * nw4) * 4;
    const float4 r0 = *(const float4*)&W[(size_t)(2 * kp) * N + n0];
    const float4 r1 = *(const float4*)&W[(size_t)(2 * kp + 1) * N + n0];
    uint32_t h[4], l[4];
    split_pack(r0.x, r1.x, h[0], l[0]);
    split_pack(r0.y, r1.y, h[1], l[1]);
    split_pack(r0.z, r1.z, h[2], l[2]);
    split_pack(r0.w, r1.w, h[3], l[3]);
    *(uint4*)&Wh[(size_t)kp * N + n0] = make_uint4(h[0], h[1], h[2], h[3]);
    *(uint4*)&Wl[(size_t)kp * N + n0] = make_uint4(l[0], l[1], l[2], l[3]);
}

// ---------------------------------------------------------------------------
// Prep: X[m][k] fp32 -> packed bf16 hi/lo transposed [k/2][m]
// ---------------------------------------------------------------------------
__global__ __launch_bounds__(256)
void split_t(const float* __restrict__ X, uint32_t* __restrict__ XTh,
             uint32_t* __restrict__ XTl, int M, int K)
{
    __shared__ float t[32][33];
    const int k0 = blockIdx.x * 32;
    const int m0 = blockIdx.y * 32;
    const int tx = threadIdx.x & 31, ty = threadIdx.x >> 5;
#pragma unroll
    for (int i = 0; i < 4; i++)
        t[ty + i * 8][tx] = X[(size_t)(m0 + ty + i * 8) * K + k0 + tx];
    __syncthreads();
#pragma unroll
    for (int i = 0; i < 2; i++) {
        const int kp = ty + i * 8;             // 0..15
        uint32_t hi, lo;
        split_pack(t[tx][2 * kp], t[tx][2 * kp + 1], hi, lo);
        const size_t dst = (size_t)(k0 / 2 + kp) * M + m0 + tx;
        XTh[dst] = hi;
        XTl[dst] = lo;
    }
}

// ---------------------------------------------------------------------------
// 3xBF16 GEMM on pre-split packed operands, cp.async double-buffered.
// A: [K/2][M] hi/lo packed words, B: [K/2][N]. 128x128 tile, k-tile = 32.
// MODE 0: +bias, scatter to g_Q / g_KTh|l(packed) / g_V.   MODE 1: dense out.
// ---------------------------------------------------------------------------
template<int MODE>
__global__ __launch_bounds__(256, 2)
void gemm_bf(const uint32_t* __restrict__ APh, const uint32_t* __restrict__ APl,
             const uint32_t* __restrict__ BPh, const uint32_t* __restrict__ BPl,
             const float* __restrict__ bias, float* __restrict__ Cout,
             int M, int N, int K)
{
    extern __shared__ uint32_t smu[];
    uint32_t* sAh = smu;                   // [2][16*PA]
    uint32_t* sAl = sAh + 2 * 16 * PA;
    uint32_t* sBh = sAl + 2 * 16 * PA;
    uint32_t* sBl = sBh + 2 * 16 * PA;

    const int tid  = threadIdx.x;
    const int lane = tid & 31;
    const int wid  = tid >> 5;
    const int mw   = (wid >> 2) * 64;
    const int nw   = (wid & 3) * 32;
    const int g    = lane >> 2;
    const int tig  = lane & 3;
    const int bm   = blockIdx.y * 128;
    const int bn   = blockIdx.x * 128;

    const uint32_t bAh = (uint32_t)__cvta_generic_to_shared(sAh);
    const uint32_t bAl = (uint32_t)__cvta_generic_to_shared(sAl);
    const uint32_t bBh = (uint32_t)__cvta_generic_to_shared(sBh);
    const uint32_t bBl = (uint32_t)__cvta_generic_to_shared(sBl);

    const int c0k = (tid + 0)   >> 5, c0m = ((tid + 0)   & 31) * 4;
    const int c1k = (tid + 256) >> 5, c1m = ((tid + 256) & 31) * 4;

    auto issue = [&](int kt) {
        const int buf = kt & 1;
        const int ko2 = kt * 16;               // word-row offset
        {
            const size_t ga = (size_t)(ko2 + c0k) * M + bm + c0m;
            const size_t gb = (size_t)(ko2 + c0k) * N + bn + c0m;
            const uint32_t so = (uint32_t)(buf * 16 * PA + c0k * PA + c0m) * 4u;
            CPA16(bAh + so, APh + ga);
            CPA16(bAl + so, APl + ga);
            CPA16(bBh + so, BPh + gb);
            CPA16(bBl + so, BPl + gb);
        }
        {
            const size_t ga = (size_t)(ko2 + c1k) * M + bm + c1m;
            const size_t gb = (size_t)(ko2 + c1k) * N + bn + c1m;
            const uint32_t so = (uint32_t)(buf * 16 * PA + c1k * PA + c1m) * 4u;
            CPA16(bAh + so, APh + ga);
            CPA16(bAl + so, APl + ga);
            CPA16(bBh + so, BPh + gb);
            CPA16(bBl + so, BPl + gb);
        }
        asm volatile("cp.async.commit_group;");
    };

    float c[4][4][4];
#pragma unroll
    for (int i = 0; i < 4; i++)
#pragma unroll
        for (int j = 0; j < 4; j++)
#pragma unroll
            for (int l = 0; l < 4; l++) c[i][j][l] = 0.f;

    const int NKT = K / 32;
    issue(0);

    for (int kt = 0; kt < NKT; kt++) {
        if (kt + 1 < NKT) {
            issue(kt + 1);
            asm volatile("cp.async.wait_group 1;");
        } else {
            asm volatile("cp.async.wait_group 0;");
        }
        __syncthreads();

        const int cur = kt & 1;
        const uint32_t* ah = sAh + cur * 16 * PA;
        const uint32_t* al = sAl + cur * 16 * PA;
        const uint32_t* bh = sBh + cur * 16 * PA;
        const uint32_t* bl = sBl + cur * 16 * PA;

#pragma unroll
        for (int ks2 = 0; ks2 < 16; ks2 += 8) {
            const int kp0 = ks2 + tig, kp1 = ks2 + tig + 4;
            uint32_t bhf[4][2], blf[4][2];
#pragma unroll
            for (int ni = 0; ni < 4; ni++) {
                const int n = nw + ni * 8 + g;
                bhf[ni][0] = bh[kp0 * PA + n];
                bhf[ni][1] = bh[kp1 * PA + n];
                blf[ni][0] = bl[kp0 * PA + n];
                blf[ni][1] = bl[kp1 * PA + n];
            }
#pragma unroll
            for (int mi = 0; mi < 4; mi++) {
                const int r0 = mw + mi * 16 + g, r1 = r0 + 8;
                const uint32_t ah0 = ah[kp0 * PA + r0];
                const uint32_t ah1 = ah[kp0 * PA + r1];
                const uint32_t ah2 = ah[kp1 * PA + r0];
                const uint32_t ah3 = ah[kp1 * PA + r1];
                const uint32_t al0 = al[kp0 * PA + r0];
                const uint32_t al1 = al[kp0 * PA + r1];
                const uint32_t al2 = al[kp1 * PA + r0];
                const uint32_t al3 = al[kp1 * PA + r1];
#pragma unroll
                for (int ni = 0; ni < 4; ni++) {
                    MMA16(c[mi][ni], ah0, ah1, ah2, ah3, bhf[ni][0], bhf[ni][1]);
                    MMA16(c[mi][ni], ah0, ah1, ah2, ah3, blf[ni][0], blf[ni][1]);
                    MMA16(c[mi][ni], al0, al1, al2, al3, bhf[ni][0], bhf[ni][1]);
                }
            }
        }
        __syncthreads();
    }

    // ---- epilogue ----
#pragma unroll
    for (int mi = 0; mi < 4; mi++) {
#pragma unroll
        for (int ni = 0; ni < 4; ni++) {
            const int r0 = bm + mw + mi * 16 + g;
            const int r1 = r0 + 8;
            const int n0 = bn + nw + ni * 8 + tig * 2;
            const float bv0 = bias[n0], bv1 = bias[n0 + 1];
            const float v00 = c[mi][ni][0] + bv0;
            const float v01 = c[mi][ni][1] + bv1;
            const float v10 = c[mi][ni][2] + bv0;
            const float v11 = c[mi][ni][3] + bv1;
            if (MODE == 1) {
                *(float2*)&Cout[(size_t)r0 * N + n0] = make_float2(v00, v01);
                *(float2*)&Cout[(size_t)r1 * N + n0] = make_float2(v10, v11);
            } else {
                const int type = n0 >> 10;
                const int e = n0 & (EMB - 1);
                const int h = e >> 6, d = e & 63;
#pragma unroll
                for (int rr = 0; rr < 2; rr++) {
                    const int m = rr ? r1 : r0;
                    const float va = rr ? v10 : v00;
                    const float vb = rr ? v11 : v01;
                    const int b = m >> 11, s = m & (SEQ - 1);
                    const size_t bhx = (size_t)(b * NH + h);
                    if (type == 0) {
                        *(float2*)&g_Q[(bhx * SEQ + s) * HD + d] = make_float2(va, vb);
                    } else if (type == 1) {
                        uint32_t hi, lo;
                        split_pack(va, vb, hi, lo);
                        const size_t ix = (bhx * (HD / 2) + (d >> 1)) * SEQ + s;
                        g_KTh[ix] = hi;
                        g_KTl[ix] = lo;
                    } else {
                        *(float2*)&g_V[(bhx * SEQ + s) * HD + d] = make_float2(va, vb);
                    }
                }
            }
        }
    }
}

// ---------------------------------------------------------------------------
// Tensor-core causal attention, two-pass recompute (R3 structure).
// QK^T in 3xBF16 (m16n8k16), P@V in 1x tf32 (m16n8k8).
// CTA = 128 q-rows of one (b,h), 8 warps, warp = 16-row band.
// ---------------------------------------------------------------------------
#define PQH 36   /* Q packed pitch (words) */
#define PKK 72   /* K packed pitch (words) */
#define PVV 72   /* V tf32 pitch */
#define PPM 68   /* P fp32 pitch */
#define O_QH 0
#define O_QL 4608
#define O_KH 9216
#define O_KL 11520
#define O_VT 13824
#define O_PM 18432
#define ATTN_SMEM_F 27136

__global__ __launch_bounds__(256)
void attn3(float* __restrict__ attw)
{
    extern __shared__ float smf[];
    uint32_t* smu = (uint32_t*)smf;

    const int tid  = threadIdx.x;
    const int lane = tid & 31;
    const int wid  = tid >> 5;
    const int g    = lane >> 2;
    const int tig  = lane & 3;
    const int band = wid * 16;
    const int q0   = (gridDim.x - 1 - blockIdx.x) * 128;  // heavy tiles first
    const int bh   = blockIdx.y;

    const float* Qg = g_Q + ((size_t)bh * SEQ + q0) * HD;
    const float* Vg = g_V + (size_t)bh * SEQ * HD;
    const size_t kb2 = (size_t)bh * (HD / 2) * SEQ;

    // ---- Q tile (128x64), scale 1/8, split -> packed bf16 hi/lo [s][d/2] ----
#pragma unroll
    for (int i = 0; i < 16; i++) {
        const int idx = tid + i * 256;
        const int r = idx >> 5, wp = idx & 31;
        float2 v = *(const float2*)&Qg[(size_t)r * HD + wp * 2];
        v.x *= 0.125f; v.y *= 0.125f;
        uint32_t hi, lo;
        split_pack(v.x, v.y, hi, lo);
        smu[O_QH + r * PQH + wp] = hi;
        smu[O_QL + r * PQH + wp] = lo;
    }

    const int nch  = (q0 >> 6) + 2;
    const int row0 = q0 + band + g;
    const int row1 = row0 + 8;
    float* Prow = attw + ((size_t)bh * SEQ + q0) * SEQ;

    float m0 = -1e30f, m1 = -1e30f, l0 = 0.f, l1 = 0.f;

    // =============================== PASS 1 ===============================
    for (int kc = 0; kc < nch; kc++) {
        const int s0 = kc * 64;
        __syncthreads();
        // K chunk: packed [d/2][key] 32x64
#pragma unroll
        for (int i = 0; i < 2; i++) {
            const int idx = tid + i * 256;
            const int kp = idx >> 4, c4 = idx & 15;
            const size_t gk = kb2 + (size_t)kp * SEQ + s0 + c4 * 4;
            *(uint4*)&smu[O_KH + kp * PKK + c4 * 4] = *(const uint4*)&g_KTh[gk];
            *(uint4*)&smu[O_KL + kp * PKK + c4 * 4] = *(const uint4*)&g_KTl[gk];
        }
        __syncthreads();

        float sc[8][4];
#pragma unroll
        for (int nf = 0; nf < 8; nf++)
#pragma unroll
            for (int j = 0; j < 4; j++) sc[nf][j] = 0.f;

#pragma unroll
        for (int ks = 0; ks < 4; ks++) {
            const int kp0 = ks * 8 + tig, kp1 = kp0 + 4;
            const uint32_t qh0 = smu[O_QH + (band + g) * PQH + kp0];
            const uint32_t qh1 = smu[O_QH + (band + g + 8) * PQH + kp0];
            const uint32_t qh2 = smu[O_QH + (band + g) * PQH + kp1];
            const uint32_t qh3 = smu[O_QH + (band + g + 8) * PQH + kp1];
            const uint32_t ql0 = smu[O_QL + (band + g) * PQH + kp0];
            const uint32_t ql1 = smu[O_QL + (band + g + 8) * PQH + kp0];
            const uint32_t ql2 = smu[O_QL + (band + g) * PQH + kp1];
            const uint32_t ql3 = smu[O_QL + (band + g + 8) * PQH + kp1];
#pragma unroll
            for (int nf = 0; nf < 8; nf++) {
                const uint32_t kh0 = smu[O_KH + kp0 * PKK + nf * 8 + g];
                const uint32_t kh1 = smu[O_KH + kp1 * PKK + nf * 8 + g];
                const uint32_t kl0 = smu[O_KL + kp0 * PKK + nf * 8 + g];
                const uint32_t kl1 = smu[O_KL + kp1 * PKK + nf * 8 + g];
                MMA16(sc[nf], qh0, qh1, qh2, qh3, kh0, kh1);
                MMA16(sc[nf], qh0, qh1, qh2, qh3, kl0, kl1);
                MMA16(sc[nf], ql0, ql1, ql2, ql3, kh0, kh1);
            }
        }

        // causal mask + online stats
        float cm0 = -1e30f, cm1 = -1e30f;
#pragma unroll
        for (int nf = 0; nf < 8; nf++) {
            const int c01 = s0 + nf * 8 + 2 * tig;
            if (c01     > row0) sc[nf][0] = -1e30f;
            if (c01 + 1 > row0) sc[nf][1] = -1e30f;
            if (c01     > row1) sc[nf][2] = -1e30f;
            if (c01 + 1 > row1) sc[nf][3] = -1e30f;
            cm0 = fmaxf(cm0, fmaxf(sc[nf][0], sc[nf][1]));
            cm1 = fmaxf(cm1, fmaxf(sc[nf][2], sc[nf][3]));
        }
        cm0 = fmaxf(cm0, __shfl_xor_sync(0xffffffffu, cm0, 1));
        cm0 = fmaxf(cm0, __shfl_xor_sync(0xffffffffu, cm0, 2));
        cm1 = fmaxf(cm1, __shfl_xor_sync(0xffffffffu, cm1, 1));
        cm1 = fmaxf(cm1, __shfl_xor_sync(0xffffffffu, cm1, 2));
        const float mn0 = fmaxf(m0, cm0), mn1 = fmaxf(m1, cm1);
        float s0a = 0.f, s1a = 0.f;
#pragma unroll
        for (int nf = 0; nf < 8; nf++) {
            s0a += __expf(sc[nf][0] - mn0) + __expf(sc[nf][1] - mn0);
            s1a += __expf(sc[nf][2] - mn1) + __expf(sc[nf][3] - mn1);
        }
        s0a += __shfl_xor_sync(0xffffffffu, s0a, 1);
        s0a += __shfl_xor_sync(0xffffffffu, s0a, 2);
        s1a += __shfl_xor_sync(0xffffffffu, s1a, 1);
        s1a += __shfl_xor_sync(0xffffffffu, s1a, 2);
        l0 = l0 * __expf(m0 - mn0) + s0a;
        l1 = l1 * __expf(m1 - mn1) + s1a;
        m0 = mn0; m1 = mn1;
    }

    const float invl0 = 1.f / l0;
    const float invl1 = 1.f / l1;

    // =============================== PASS 2 ===============================
    float co[8][4];
#pragma unroll
    for (int df = 0; df < 8; df++)
#pragma unroll
        for (int j = 0; j < 4; j++) co[df][j] = 0.f;

    for (int kc = 0; kc < nch; kc++) {
        const int s0 = kc * 64;
        __syncthreads();
        // K chunk + V chunk (tf32 [key][d])
#pragma unroll
        for (int i = 0; i < 2; i++) {
            const int idx = tid + i * 256;
            const int kp = idx >> 4, c4 = idx & 15;
            const size_t gk = kb2 + (size_t)kp * SEQ + s0 + c4 * 4;
            *(uint4*)&smu[O_KH + kp * PKK + c4 * 4] = *(const uint4*)&g_KTh[gk];
            *(uint4*)&smu[O_KL + kp * PKK + c4 * 4] = *(const uint4*)&g_KTl[gk];
        }
#pragma unroll
        for (int i = 0; i < 4; i++) {
            const int idx = tid + i * 256;
            const int key = idx >> 4, c4 = idx & 15;
            const float4 vv = *(const float4*)&Vg[(size_t)(s0 + key) * HD + c4 * 4];
            *(uint4*)&smu[O_VT + key * PVV + c4 * 4] =
                make_uint4(f2tf32(vv.x), f2tf32(vv.y), f2tf32(vv.z), f2tf32(vv.w));
        }
        __syncthreads();

        float sc[8][4];
#pragma unroll
        for (int nf = 0; nf < 8; nf++)
#pragma unroll
            for (int j = 0; j < 4; j++) sc[nf][j] = 0.f;

#pragma unroll
        for (int ks = 0; ks < 4; ks++) {
            const int kp0 = ks * 8 + tig, kp1 = kp0 + 4;
            const uint32_t qh0 = smu[O_QH + (band + g) * PQH + kp0];
            const uint32_t qh1 = smu[O_QH + (band + g + 8) * PQH + kp0];
            const uint32_t qh2 = smu[O_QH + (band + g) * PQH + kp1];
            const uint32_t qh3 = smu[O_QH + (band + g + 8) * PQH + kp1];
            const uint32_t ql0 = smu[O_QL + (band + g) * PQH + kp0];
            const uint32_t ql1 = smu[O_QL + (band + g + 8) * PQH + kp0];
            const uint32_t ql2 = smu[O_QL + (band + g) * PQH + kp1];
            const uint32_t ql3 = smu[O_QL + (band + g + 8) * PQH + kp1];
#pragma unroll
            for (int nf = 0; nf < 8; nf++) {
                const uint32_t kh0 = smu[O_KH + kp0 * PKK + nf * 8 + g];
                const uint32_t kh1 = smu[O_KH + kp1 * PKK + nf * 8 + g];
                const uint32_t kl0 = smu[O_KL + kp0 * PKK + nf * 8 + g];
                const uint32_t kl1 = smu[O_KL + kp1 * PKK + nf * 8 + g];
                MMA16(sc[nf], qh0, qh1, qh2, qh3, kh0, kh1);
                MMA16(sc[nf], qh0, qh1, qh2, qh3, kl0, kl1);
                MMA16(sc[nf], ql0, ql1, ql2, ql3, kh0, kh1);
            }
        }

        // P = exp(s - m) / l  (masked -> 0), store to smem
#pragma unroll
        for (int nf = 0; nf < 8; nf++) {
            const int c01 = s0 + nf * 8 + 2 * tig;
            if (c01     > row0) sc[nf][0] = -1e30f;
            if (c01 + 1 > row0) sc[nf][1] = -1e30f;
            if (c01     > row1) sc[nf][2] = -1e30f;
            if (c01 + 1 > row1) sc[nf][3] = -1e30f;
            const float p0 = __expf(sc[nf][0] - m0) * invl0;
            const float p1 = __expf(sc[nf][1] - m0) * invl0;
            const float p2 = __expf(sc[nf][2] - m1) * invl1;
            const float p3 = __expf(sc[nf][3] - m1) * invl1;
            *(float2*)&smf[O_PM + (band + g) * PPM + nf * 8 + 2 * tig]     = make_float2(p0, p1);
            *(float2*)&smf[O_PM + (band + g + 8) * PPM + nf * 8 + 2 * tig] = make_float2(p2, p3);
        }
        __syncthreads();

        // O += P @ V  (1x tf32)
#pragma unroll
        for (int k8 = 0; k8 < 8; k8++) {
            const int ka = k8 * 8 + tig;
            const uint32_t a0 = f2tf32(smf[O_PM + (band + g) * PPM + ka]);
            const uint32_t a1 = f2tf32(smf[O_PM + (band + g + 8) * PPM + ka]);
            const uint32_t a2 = f2tf32(smf[O_PM + (band + g) * PPM + ka + 4]);
            const uint32_t a3 = f2tf32(smf[O_PM + (band + g + 8) * PPM + ka + 4]);
#pragma unroll
            for (int df = 0; df < 8; df++) {
                const uint32_t b0 = smu[O_VT + ka * PVV + df * 8 + g];
                const uint32_t b1 = smu[O_VT + (ka + 4) * PVV + df * 8 + g];
                MMA8(co[df], a0, a1, a2, a3, b0, b1);
            }
        }

        // write P chunk to gmem (coalesced float4)
#pragma unroll
        for (int i = 0; i < 8; i++) {
            const int idx = tid + i * 256;
            const int r = idx >> 4, c4 = idx & 15;
            *(float4*)&Prow[(size_t)r * SEQ + s0 + c4 * 4] =
                *(float4*)&smf[O_PM + r * PPM + c4 * 4];
        }
    }

    // ---- zero tail of attention_weights ----
    {
        const int ztail = nch * 64;                // == q0 + 128
        const int ncol4 = (SEQ - ztail) >> 2;
        const float4 z = make_float4(0.f, 0.f, 0.f, 0.f);
        for (int idx = tid; idx < 128 * ncol4; idx += 256) {
            const int r = idx / ncol4, c = idx - r * ncol4;
            *(float4*)&Prow[(size_t)r * SEQ + ztail + c * 4] = z;
        }
    }

    // ---- write O ----
    {
        const int b = bh >> 4, h = bh & 15;
#pragma unroll
        for (int df = 0; df < 8; df++) {
            const int d = h * 64 + df * 8 + 2 * tig;
            *(float2*)&g_AO[(size_t)(b * SEQ + row0) * EMB + d] = make_float2(co[df][0], co[df][1]);
            *(float2*)&g_AO[(size_t)(b * SEQ + row1) * EMB + d] = make_float2(co[df][2], co[df][3]);
        }
    }
}

// ---------------------------------------------------------------------------
extern "C" void kernel_launch(void* const* d_in, const int* in_sizes, int n_in,
                              void* d_out, int out_size)
{
    const float* x    = (const float*)d_in[0];
    const float* Wqkv = (const float*)d_in[1];
    const float* bqkv = (const float*)d_in[2];
    const float* Wout = (const float*)d_in[3];
    const float* bout = (const float*)d_in[4];

    float* out  = (float*)d_out;
    float* attw = out + (size_t)BATCH * SEQ * EMB;

    uint32_t *p_xth, *p_xtl, *p_aoth, *p_aotl, *p_wqh, *p_wql, *p_woh, *p_wol;
    cudaGetSymbolAddress((void**)&p_xth,  g_xth);
    cudaGetSymbolAddress((void**)&p_xtl,  g_xtl);
    cudaGetSymbolAddress((void**)&p_aoth, g_aoth);
    cudaGetSymbolAddress((void**)&p_aotl, g_aotl);
    cudaGetSymbolAddress((void**)&p_wqh,  g_wqh);
    cudaGetSymbolAddress((void**)&p_wql,  g_wql);
    cudaGetSymbolAddress((void**)&p_woh,  g_woh);
    cudaGetSymbolAddress((void**)&p_wol,  g_wol);
    float* p_ao;
    cudaGetSymbolAddress((void**)&p_ao, g_AO);

    const int gsmem = 8 * 16 * PA * (int)sizeof(uint32_t);   // 69632
    cudaFuncSetAttribute(gemm_bf<0>, cudaFuncAttributeMaxDynamicSharedMemorySize, gsmem);
    cudaFuncSetAttribute(gemm_bf<1>, cudaFuncAttributeMaxDynamicSharedMemorySize, gsmem);
    const int asmem = ATTN_SMEM_F * (int)sizeof(float);      // 108544
    cudaFuncSetAttribute(attn3, cudaFuncAttributeMaxDynamicSharedMemorySize, asmem);

    // prep: pack weights + pack-transpose x
    split_w<<<((KDIM / 2) * (N1 / 4) + 255) / 256, 256>>>(Wqkv, p_wqh, p_wql, N1, (KDIM / 2) * (N1 / 4));
    split_w<<<((KDIM / 2) * (EMB / 4) + 255) / 256, 256>>>(Wout, p_woh, p_wol, EMB, (KDIM / 2) * (EMB / 4));
    split_t<<<dim3(KDIM / 32, M1 / 32), 256>>>(x, p_xth, p_xtl, M1, KDIM);

    // 1) QKV projection
    gemm_bf<0><<<dim3(N1 / 128, M1 / 128), 256, gsmem>>>(p_xth, p_xtl, p_wqh, p_wql, bqkv, nullptr, M1, N1, KDIM);

    // 2) fused causal attention (writes attention_weights)
    attn3<<<dim3(SEQ / 128, BATCH * NH), 256, asmem>>>(attw);

    // prep: pack-transpose attended output
    split_t<<<dim3(KDIM / 32, M1 / 32), 256>>>(p_ao, p_aoth, p_aotl, M1, KDIM);

    // 3) output projection
    gemm_bf<1><<<dim3(EMB / 128, M1 / 128), 256, gsmem>>>(p_aoth, p_aotl, p_woh, p_wol, bout, out, M1, EMB, KDIM);
}